// round 8
// baseline (speedup 1.0000x reference)
#include <cuda_runtime.h>
#include <cuda_bf16.h>
#include <cuda_fp16.h>

#define D     64
#define C     256
#define RDIM  128
#define NPTS  100000
#define GRID_VOX (D*D*D)

typedef unsigned long long ull;

// ---- scratch (device globals; BSS zero-initialized; no allocation) ----
__device__ int   g_idx[GRID_VOX];                 // (x*64+y)*64+z -> point+1, 0=empty
__device__ int   g_idxT[GRID_VOX];                // (z*64+x)*64+y -> point+1
__device__ uint4 g_bufA_h[(size_t)GRID_VOX * 32]; // z-pooled grid, fp16
__device__ uint4 g_y4[(size_t)NPTS * 32];         // pooled, compacted, fp16

#define NEGH 0xFC00FC00u
__device__ __forceinline__ uint4 negh4() { return make_uint4(NEGH, NEGH, NEGH, NEGH); }

__device__ __forceinline__ unsigned h2max(unsigned a, unsigned b) {
    __half2 r = __hmax2(*reinterpret_cast<__half2*>(&a),
                        *reinterpret_cast<__half2*>(&b));
    return *reinterpret_cast<unsigned*>(&r);
}
__device__ __forceinline__ uint4 hmax4(uint4 a, uint4 b) {
    return make_uint4(h2max(a.x, b.x), h2max(a.y, b.y),
                      h2max(a.z, b.z), h2max(a.w, b.w));
}
__device__ __forceinline__ unsigned pack2(float a, float b) {
    __half2 h = __floats2half2_rn(a, b);
    return *reinterpret_cast<unsigned*>(&h);
}

// ===========================================================================
// scatter (no init needed: 0 = empty, value = point index + 1)
// ===========================================================================
__global__ void scatter_idx_kernel(const int* __restrict__ coords) {
    int n = blockIdx.x * blockDim.x + threadIdx.x;
    if (n < NPTS) {
        int ix = coords[3*n+0], iy = coords[3*n+1], iz = coords[3*n+2];
        g_idx[(ix*D + iy)*D + iz] = n + 1;
        g_idxT[(iz*D + ix)*D + iy] = n + 1;
    }
}

// ===========================================================================
// z-pass
// ===========================================================================
__device__ __forceinline__ uint4 load_point_h(const float* __restrict__ feats,
                                              int vox, int c2) {
    int e = g_idx[vox];
    if (e == 0) return negh4();
    const float4* p = (const float4*)(feats + (size_t)(e - 1) * C + c2 * 8);
    float4 f0 = __ldg(p), f1 = __ldg(p + 1);
    return make_uint4(pack2(f0.x, f0.y), pack2(f0.z, f0.w),
                      pack2(f1.x, f1.y), pack2(f1.z, f1.w));
}
__global__ void pool_z_kernel(const float* __restrict__ feats) {
    int c2   = threadIdx.x;
    int pair = blockIdx.x * blockDim.y + threadIdx.y;
    int voxbase = pair * D;
    uint4 NEG = negh4();
    uint4 w0 = NEG, w1 = NEG, w2 = NEG;
    uint4 w3 = load_point_h(feats, voxbase + 0, c2);
    uint4 w4 = load_point_h(feats, voxbase + 1, c2);
    uint4 w5 = load_point_h(feats, voxbase + 2, c2);
    uint4* out = g_bufA_h + (size_t)voxbase * 32 + c2;
    #pragma unroll 4
    for (int z = 0; z < D; z++) {
        uint4 nxt = (z + 3 < D) ? load_point_h(feats, voxbase + z + 3, c2) : NEG;
        uint4 m = hmax4(hmax4(hmax4(w0, w1), hmax4(w2, w3)),
                        hmax4(hmax4(w4, w5), nxt));
        out[(size_t)z * 32] = m;
        w0 = w1; w1 = w2; w2 = w3; w3 = w4; w4 = w5; w5 = nxt;
    }
}

// ===========================================================================
// fused y+x pass (two-phase)
// ===========================================================================
#define POOL_SMEM (64*65*16 + 4096)

__global__ void __launch_bounds__(256, 2)
pool_yx_kernel() {
    extern __shared__ uint4 ym[];
    int* idx_s = (int*)(ym + 64 * 65);

    int bid = blockIdx.x;
    int z   = bid & 63;
    int cg  = (bid >> 6) & 7;
    int y0  = (bid >> 9) * 16;
    int tid = threadIdx.x;
    uint4 NEG = negh4();

    {
        int x = tid >> 2, cq = tid & 3;
        const uint4* src = g_bufA_h + ((size_t)(x * 64) * 64 + z) * 32 + cg * 4 + cq;
        uint4 w0, w1, w2, w3, w4, w5;
        w0 = (y0 - 3 >= 0) ? src[(size_t)(y0 - 3) * 2048] : NEG;
        w1 = (y0 - 2 >= 0) ? src[(size_t)(y0 - 2) * 2048] : NEG;
        w2 = (y0 - 1 >= 0) ? src[(size_t)(y0 - 1) * 2048] : NEG;
        w3 = src[(size_t)(y0 + 0) * 2048];
        w4 = src[(size_t)(y0 + 1) * 2048];
        w5 = src[(size_t)(y0 + 2) * 2048];
        #pragma unroll 8
        for (int y = 0; y < 16; y++) {
            int yg = y0 + y + 3;
            uint4 nxt = (yg < 64) ? src[(size_t)yg * 2048] : NEG;
            uint4 m = hmax4(hmax4(hmax4(w0, w1), hmax4(w2, w3)),
                            hmax4(hmax4(w4, w5), nxt));
            ym[x * 65 + y * 4 + cq] = m;
            w0 = w1; w1 = w2; w2 = w3; w3 = w4; w4 = w5; w5 = nxt;
        }
    }
    for (int i = tid; i < 1024; i += 256) {
        int x = i >> 4, yy = i & 15;
        idx_s[i] = g_idxT[(z * 64 + x) * 64 + y0 + yy];
    }
    __syncthreads();

    {
        int cq = tid & 3, y = (tid >> 2) & 15, xq = tid >> 6;
        int x0 = xq * 16;
        int off = y * 4 + cq;
        uint4 w0, w1, w2, w3, w4, w5;
        w0 = (x0 - 3 >= 0) ? ym[(x0 - 3) * 65 + off] : NEG;
        w1 = (x0 - 2 >= 0) ? ym[(x0 - 2) * 65 + off] : NEG;
        w2 = (x0 - 1 >= 0) ? ym[(x0 - 1) * 65 + off] : NEG;
        w3 = ym[(x0 + 0) * 65 + off];
        w4 = ym[(x0 + 1) * 65 + off];
        w5 = ym[(x0 + 2) * 65 + off];
        #pragma unroll 4
        for (int xx = x0; xx < x0 + 16; xx++) {
            uint4 nxt = (xx + 3 < 64) ? ym[(xx + 3) * 65 + off] : NEG;
            int e = idx_s[xx * 16 + y];
            if (e > 0) {
                uint4 m = hmax4(hmax4(hmax4(w0, w1), hmax4(w2, w3)),
                                hmax4(hmax4(w4, w5), nxt));
                g_y4[(size_t)(e - 1) * 32 + cg * 4 + cq] = m;
            }
            w0 = w1; w1 = w2; w2 = w3; w3 = w4; w4 = w5; w5 = nxt;
        }
    }
}

// ===========================================================================
// Hybrid MLP: per-CTA path switch (tensor fp16 mma / packed f32x2 FFMA)
// ===========================================================================
// ----- shared helpers -----
__device__ __forceinline__ void mma16(float* c, unsigned a0, unsigned a1,
                                      unsigned a2, unsigned a3,
                                      unsigned b0, unsigned b1) {
    asm("mma.sync.aligned.m16n8k16.row.col.f32.f16.f16.f32 "
        "{%0,%1,%2,%3}, {%4,%5,%6,%7}, {%8,%9}, {%0,%1,%2,%3};"
        : "+f"(c[0]), "+f"(c[1]), "+f"(c[2]), "+f"(c[3])
        : "r"(a0), "r"(a1), "r"(a2), "r"(a3), "r"(b0), "r"(b1));
}
__device__ __forceinline__ void ffma2(ull& d, ull a, ull b) {
    asm("fma.rn.f32x2 %0, %1, %2, %0;" : "+l"(d) : "l"(a), "l"(b));
}
__device__ __forceinline__ ull pk64(float x, float y) {
    ull r; asm("mov.b64 %0, {%1,%2};" : "=l"(r) : "f"(x), "f"(y)); return r;
}
__device__ __forceinline__ void upk64(float& x, float& y, ull v) {
    asm("mov.b64 {%0,%1}, %2;" : "=f"(x), "=f"(y) : "l"(v));
}

// ----- tensor path (unchanged from R7) -----
#define OFF_XS0 0
#define OFF_XS1 8192
#define OFF_WS0 16384
#define OFF_WS1 24576
#define OFF_HS  0
#define OFF_C0  32768
#define OFF_C1  40960

__device__ __forceinline__ void t_compute(const uint4* __restrict__ A4,
                                          const uint2* __restrict__ B2,
                                          int wm, int wn, int lane,
                                          float acc[2][8][4]) {
    #pragma unroll
    for (int ks = 0; ks < 2; ks++) {
        uint4 a0 = A4[((wm * 2 + 0) * 2 + ks) * 32 + lane];
        uint4 a1 = A4[((wm * 2 + 1) * 2 + ks) * 32 + lane];
        #pragma unroll
        for (int nt = 0; nt < 8; nt++) {
            uint2 b = B2[((wn * 8 + nt) * 2 + ks) * 32 + lane];
            mma16(acc[0][nt], a0.x, a0.y, a0.z, a0.w, b.x, b.y);
            mma16(acc[1][nt], a1.x, a1.y, a1.z, a1.w, b.x, b.y);
        }
    }
}
__device__ __forceinline__ void t_ldg_X(uint4 v[2], int tid, int row0, int kt) {
    #pragma unroll
    for (int u = 0; u < 2; u++) {
        int id = tid + u * 256;
        int r = id >> 2, c8 = id & 3;
        v[u] = (row0 + r < NPTS)
             ? g_y4[(size_t)(row0 + r) * 32 + kt * 4 + c8]
             : make_uint4(0, 0, 0, 0);
    }
}
__device__ __forceinline__ void t_sts_X(unsigned* X32, int tid, const uint4 v[2]) {
    #pragma unroll
    for (int u = 0; u < 2; u++) {
        int id = tid + u * 256;
        int r = id >> 2, c8 = id & 3;
        int mb = r >> 4, g = r & 7, rb = (r >> 3) & 1;
        int ksc = c8 >> 1, kbit = c8 & 1;
        int sbase = (mb * 2 + ksc) * 32 + g * 4;
        int comp = rb + 2 * kbit;
        unsigned vv[4] = {v[u].x, v[u].y, v[u].z, v[u].w};
        #pragma unroll
        for (int j = 0; j < 4; j++)
            X32[(sbase + j) * 4 + comp] = vv[j];
    }
}
__device__ __forceinline__ void t_ldg_W(float4 v[4], int tid,
                                        const float* __restrict__ W, int ldw,
                                        int kt, int ncol0) {
    #pragma unroll
    for (int u = 0; u < 4; u++) {
        int e = tid + u * 256;
        int k = e >> 5, n4 = e & 31;
        v[u] = *(const float4*)(W + (size_t)(kt * 32 + k) * ldw + ncol0 + n4 * 4);
    }
}
__device__ __forceinline__ void t_sts_W(unsigned short* W16, int tid,
                                        const float4 v[4]) {
    #pragma unroll
    for (int u = 0; u < 4; u++) {
        int e = tid + u * 256;
        int k = e >> 5, n4 = e & 31;
        int ksc = (k >> 4) & 1, kbit = (k & 15) >> 3;
        int tg = (k & 7) >> 1, elem = k & 1;
        float vv[4] = {v[u].x, v[u].y, v[u].z, v[u].w};
        #pragma unroll
        for (int i = 0; i < 4; i++) {
            int n = n4 * 4 + i;
            int slot = ((n >> 3) * 2 + ksc) * 32 + (n & 7) * 4 + tg;
            W16[slot * 4 + kbit * 2 + elem] =
                __half_as_ushort(__float2half_rn(vv[i]));
        }
    }
}

__device__ void tensor_path(char* smb, int tid, int row0,
                            const float* __restrict__ feats,
                            const float* __restrict__ W1,
                            const float* __restrict__ W2,
                            float* __restrict__ out) {
    unsigned*       X32b[2] = {(unsigned*)(smb + OFF_XS0), (unsigned*)(smb + OFF_XS1)};
    unsigned short* W16b[2] = {(unsigned short*)(smb + OFF_WS0),
                               (unsigned short*)(smb + OFF_WS1)};
    unsigned short* C16b[2] = {(unsigned short*)(smb + OFF_C0),
                               (unsigned short*)(smb + OFF_C1)};
    unsigned* HS32 = (unsigned*)(smb + OFF_HS);

    int lane = tid & 31, wid = tid >> 5;
    int wm = wid >> 1, wn = wid & 1;
    int g = lane >> 2, tg = lane & 3;

    uint4  vx[2];
    float4 vw[4];
    float acc[2][8][4];

    #pragma unroll
    for (int mt = 0; mt < 2; mt++)
        #pragma unroll
        for (int nt = 0; nt < 8; nt++)
            #pragma unroll
            for (int q = 0; q < 4; q++) acc[mt][nt][q] = 0.f;

    t_ldg_X(vx, tid, row0, 0);
    t_ldg_W(vw, tid, W1, RDIM, 0, 0);
    t_sts_X(X32b[0], tid, vx);
    t_sts_W(W16b[0], tid, vw);
    __syncthreads();

    for (int kt = 0; kt < 8; kt++) {
        if (kt < 7) {
            t_ldg_X(vx, tid, row0, kt + 1);
            t_ldg_W(vw, tid, W1, RDIM, kt + 1, 0);
        }
        t_compute((const uint4*)X32b[kt & 1], (const uint2*)W16b[kt & 1],
                  wm, wn, lane, acc);
        if (kt < 7) {
            t_sts_X(X32b[(kt + 1) & 1], tid, vx);
            t_sts_W(W16b[(kt + 1) & 1], tid, vw);
        }
        __syncthreads();
    }

    #pragma unroll
    for (int mt = 0; mt < 2; mt++) {
        #pragma unroll
        for (int nt = 0; nt < 8; nt++) {
            int mb = wm * 2 + mt;
            int kc = wn * 2 + (nt >> 2);
            unsigned* Hc = HS32 + kc * 2048;
            int slot = (mb * 2 + ((nt & 3) >> 1)) * 32 + g * 4 + tg;
            Hc[slot * 4 + 2 * (nt & 1)] =
                pack2(fmaxf(acc[mt][nt][0], 0.f), fmaxf(acc[mt][nt][1], 0.f));
            Hc[slot * 4 + 1 + 2 * (nt & 1)] =
                pack2(fmaxf(acc[mt][nt][2], 0.f), fmaxf(acc[mt][nt][3], 0.f));
        }
    }
    __syncthreads();

    for (int half = 0; half < 2; half++) {
        #pragma unroll
        for (int mt = 0; mt < 2; mt++)
            #pragma unroll
            for (int nt = 0; nt < 8; nt++)
                #pragma unroll
                for (int q = 0; q < 4; q++) acc[mt][nt][q] = 0.f;

        t_ldg_W(vw, tid, W2, C, 0, half * 128);
        t_sts_W(C16b[0], tid, vw);
        __syncthreads();

        for (int kc = 0; kc < 4; kc++) {
            if (kc < 3) t_ldg_W(vw, tid, W2, C, kc + 1, half * 128);
            t_compute((const uint4*)(HS32 + kc * 2048),
                      (const uint2*)C16b[kc & 1], wm, wn, lane, acc);
            if (kc < 3) t_sts_W(C16b[(kc + 1) & 1], tid, vw);
            __syncthreads();
        }

        #pragma unroll
        for (int mt = 0; mt < 2; mt++) {
            #pragma unroll
            for (int nt = 0; nt < 8; nt++) {
                int rr = wm * 32 + mt * 16 + g;
                int cc = half * 128 + wn * 64 + nt * 8 + 2 * tg;
                #pragma unroll
                for (int h = 0; h < 2; h++) {
                    int row = row0 + rr + h * 8;
                    if (row < NPTS) {
                        float z0 = acc[mt][nt][h * 2 + 0];
                        float z1 = acc[mt][nt][h * 2 + 1];
                        float2 fv = *(const float2*)(feats + (size_t)row * C + cc);
                        float2 o;
                        o.x = fv.x / (1.f + __expf(-z0));
                        o.y = fv.y / (1.f + __expf(-z1));
                        *(float2*)(out + (size_t)row * C + cc) = o;
                    }
                }
            }
        }
    }
}

// ----- f32x2 path: fp32 SGEMM with packed FFMA2, k-major smem tiles -----
#define KS 132                 // float stride per k-row
#define FX0 0                  // bytes
#define FX1 16896
#define FW0 33792
#define FW1 50688
#define FHS 0                  // 128*132*4 = 67584, aliases FX/FW
#define FC0 67584
#define FC1 84480
#define HYB_SMEM 101376

__device__ __forceinline__ void f_ldg_X(uint4 v[2], int tid, int row0, int kt) {
    int r = tid & 127, half = tid >> 7;
    int row = row0 + r;
    if (row < NPTS) {
        const uint4* p = g_y4 + (size_t)row * 32 + kt * 4 + half * 2;
        v[0] = p[0]; v[1] = p[1];
    } else {
        v[0] = v[1] = make_uint4(0, 0, 0, 0);
    }
}
__device__ __forceinline__ void f_sts_X(float* Xs, int tid, const uint4 v[2]) {
    int r = tid & 127, half = tid >> 7;
    float* dst = Xs + half * 16 * KS + r;
    unsigned w[8] = {v[0].x, v[0].y, v[0].z, v[0].w,
                     v[1].x, v[1].y, v[1].z, v[1].w};
    #pragma unroll
    for (int q = 0; q < 8; q++) {
        float2 f = __half22float2(*reinterpret_cast<const __half2*>(&w[q]));
        dst[(q * 2 + 0) * KS] = f.x;
        dst[(q * 2 + 1) * KS] = f.y;
    }
}
__device__ __forceinline__ void f_ldg_W(float4 v[4], int tid,
                                        const float* __restrict__ W, int ldw,
                                        int kt, int ncol0) {
    #pragma unroll
    for (int u = 0; u < 4; u++) {
        int e = tid + u * 256;
        int k = e >> 5, n4 = e & 31;
        v[u] = *(const float4*)(W + (size_t)(kt * 32 + k) * ldw + ncol0 + n4 * 4);
    }
}
__device__ __forceinline__ void f_sts_W(float* Ws, int tid, const float4 v[4]) {
    #pragma unroll
    for (int u = 0; u < 4; u++) {
        int e = tid + u * 256;
        int k = e >> 5, n4 = e & 31;
        *(float4*)(Ws + k * KS + n4 * 4) = v[u];
    }
}
__device__ __forceinline__ void f_compute(const float* __restrict__ Xs,
                                          const float* __restrict__ Ws,
                                          int tx, int ty, ull acc[8][4]) {
    #pragma unroll 4
    for (int k = 0; k < 32; k++) {
        const float4* ap = (const float4*)(Xs + k * KS + ty * 8);
        float4 a0 = ap[0], a1 = ap[1];
        const float4* bp = (const float4*)(Ws + k * KS + tx * 8);
        float4 b0 = bp[0], b1 = bp[1];
        ull bv[4] = {pk64(b0.x, b0.y), pk64(b0.z, b0.w),
                     pk64(b1.x, b1.y), pk64(b1.z, b1.w)};
        float av[8] = {a0.x, a0.y, a0.z, a0.w, a1.x, a1.y, a1.z, a1.w};
        #pragma unroll
        for (int i = 0; i < 8; i++) {
            ull ad = pk64(av[i], av[i]);
            #pragma unroll
            for (int j = 0; j < 4; j++) ffma2(acc[i][j], ad, bv[j]);
        }
    }
}

__device__ void fma_path(char* smb, int tid, int row0,
                         const float* __restrict__ feats,
                         const float* __restrict__ W1,
                         const float* __restrict__ W2,
                         float* __restrict__ out) {
    float* Xb[2] = {(float*)(smb + FX0), (float*)(smb + FX1)};
    float* Wb[2] = {(float*)(smb + FW0), (float*)(smb + FW1)};
    float* Cb[2] = {(float*)(smb + FC0), (float*)(smb + FC1)};
    float* HS    = (float*)(smb + FHS);

    int tx = tid & 15, ty = tid >> 4;

    uint4  vx[2];
    float4 vw[4];
    ull acc[8][4];

    // ---------------- GEMM1: H = relu(Y @ W1), K=256, 8 chunks --------------
    #pragma unroll
    for (int i = 0; i < 8; i++)
        #pragma unroll
        for (int j = 0; j < 4; j++) acc[i][j] = 0ull;

    f_ldg_X(vx, tid, row0, 0);
    f_ldg_W(vw, tid, W1, RDIM, 0, 0);
    f_sts_X(Xb[0], tid, vx);
    f_sts_W(Wb[0], tid, vw);
    __syncthreads();

    for (int kt = 0; kt < 8; kt++) {
        if (kt < 7) {
            f_ldg_X(vx, tid, row0, kt + 1);
            f_ldg_W(vw, tid, W1, RDIM, kt + 1, 0);
        }
        f_compute(Xb[kt & 1], Wb[kt & 1], tx, ty, acc);
        if (kt < 7) {
            f_sts_X(Xb[(kt + 1) & 1], tid, vx);
            f_sts_W(Wb[(kt + 1) & 1], tid, vw);
        }
        __syncthreads();
    }

    // relu -> HS[h][row] (aliases X/W bufs; all reads done after final sync)
    #pragma unroll
    for (int i = 0; i < 8; i++) {
        int row = ty * 8 + i;
        #pragma unroll
        for (int j = 0; j < 4; j++) {
            float x, y; upk64(x, y, acc[i][j]);
            HS[(tx * 8 + 2 * j + 0) * KS + row] = fmaxf(x, 0.f);
            HS[(tx * 8 + 2 * j + 1) * KS + row] = fmaxf(y, 0.f);
        }
    }
    __syncthreads();

    // ------------- GEMM2: O = H @ W2 (K=128), two 128-col halves ------------
    for (int half = 0; half < 2; half++) {
        #pragma unroll
        for (int i = 0; i < 8; i++)
            #pragma unroll
            for (int j = 0; j < 4; j++) acc[i][j] = 0ull;

        f_ldg_W(vw, tid, W2, C, 0, half * 128);
        f_sts_W(Cb[0], tid, vw);
        __syncthreads();

        for (int kc = 0; kc < 4; kc++) {
            if (kc < 3) f_ldg_W(vw, tid, W2, C, kc + 1, half * 128);
            f_compute(HS + kc * 32 * KS, Cb[kc & 1], tx, ty, acc);
            if (kc < 3) f_sts_W(Cb[(kc + 1) & 1], tid, vw);
            __syncthreads();
        }

        // epilogue
        #pragma unroll
        for (int i = 0; i < 8; i++) {
            int row = row0 + ty * 8 + i;
            if (row < NPTS) {
                #pragma unroll
                for (int j = 0; j < 4; j++) {
                    int cc = half * 128 + tx * 8 + 2 * j;
                    float z0, z1; upk64(z0, z1, acc[i][j]);
                    float2 fv = *(const float2*)(feats + (size_t)row * C + cc);
                    float2 o;
                    o.x = fv.x / (1.f + __expf(-z0));
                    o.y = fv.y / (1.f + __expf(-z1));
                    *(float2*)(out + (size_t)row * C + cc) = o;
                }
            }
        }
    }
}

__global__ void __launch_bounds__(256, 2)
mlp_hybrid_kernel(const float* __restrict__ feats,
                  const float* __restrict__ W1,
                  const float* __restrict__ W2,
                  float* __restrict__ out) {
    extern __shared__ char smb[];
    int tid = threadIdx.x;
    int bid = blockIdx.x;
    int row0 = bid * 128;
    int m = bid & 7;
    bool use_tensor = (m == 1) || (m == 4) || (m == 6);   // 3/8 tensor
    if (use_tensor)
        tensor_path(smb, tid, row0, feats, W1, W2, out);
    else
        fma_path(smb, tid, row0, feats, W1, W2, out);
}

// ===========================================================================
extern "C" void kernel_launch(void* const* d_in, const int* in_sizes, int n_in,
                              void* d_out, int out_size) {
    const float* feats  = (const float*)d_in[0];
    const int*   coords = (const int*)d_in[1];
    const float* W1     = (const float*)d_in[2];
    const float* W2     = (const float*)d_in[3];
    float*       out    = (float*)d_out;

    scatter_idx_kernel<<<(NPTS + 255)/256, 256>>>(coords);

    dim3 zt(32, 8);
    pool_z_kernel<<<D*D/8, zt>>>(feats);

    cudaFuncSetAttribute(pool_yx_kernel,
                         cudaFuncAttributeMaxDynamicSharedMemorySize, POOL_SMEM);
    pool_yx_kernel<<<64 * 8 * 4, 256, POOL_SMEM>>>();

    cudaFuncSetAttribute(mlp_hybrid_kernel,
                         cudaFuncAttributeMaxDynamicSharedMemorySize, HYB_SMEM);
    mlp_hybrid_kernel<<<(NPTS + 127)/128, 256, HYB_SMEM>>>(feats, W1, W2, out);
}

// round 13
// speedup vs baseline: 1.0329x; 1.0329x over previous
#include <cuda_runtime.h>
#include <cuda_bf16.h>
#include <cuda_fp16.h>

#define D     64
#define C     256
#define RDIM  128
#define NPTS  100000
#define GRID_VOX (D*D*D)

typedef unsigned long long ull;

// ---- scratch (device globals; BSS zero-initialized; no allocation) ----
__device__ int   g_idx[GRID_VOX];                 // (x*64+y)*64+z -> point+1, 0=empty
__device__ int   g_idxT[GRID_VOX];                // (z*64+x)*64+y -> point+1
__device__ uint4 g_bufA_h[(size_t)GRID_VOX * 32]; // z-pooled grid, fp16
__device__ uint4 g_y4[(size_t)NPTS * 32];         // pooled, compacted, fp16

#define NEGH 0xFC00FC00u
__device__ __forceinline__ uint4 negh4() { return make_uint4(NEGH, NEGH, NEGH, NEGH); }

__device__ __forceinline__ unsigned h2max(unsigned a, unsigned b) {
    __half2 r = __hmax2(*reinterpret_cast<__half2*>(&a),
                        *reinterpret_cast<__half2*>(&b));
    return *reinterpret_cast<unsigned*>(&r);
}
__device__ __forceinline__ uint4 hmax4(uint4 a, uint4 b) {
    return make_uint4(h2max(a.x, b.x), h2max(a.y, b.y),
                      h2max(a.z, b.z), h2max(a.w, b.w));
}
__device__ __forceinline__ unsigned pack2(float a, float b) {
    __half2 h = __floats2half2_rn(a, b);
    return *reinterpret_cast<unsigned*>(&h);
}

// ===========================================================================
// scatter (0 = empty, value = point index + 1; BSS gives the zero init)
// ===========================================================================
__global__ void scatter_idx_kernel(const int* __restrict__ coords) {
    int n = blockIdx.x * blockDim.x + threadIdx.x;
    if (n < NPTS) {
        int ix = coords[3*n+0], iy = coords[3*n+1], iz = coords[3*n+2];
        g_idx[(ix*D + iy)*D + iz] = n + 1;
        g_idxT[(iz*D + ix)*D + iy] = n + 1;
    }
}

// ===========================================================================
// z-pass
// ===========================================================================
__device__ __forceinline__ uint4 load_point_h(const float* __restrict__ feats,
                                              int vox, int c2) {
    int e = g_idx[vox];
    if (e == 0) return negh4();
    const float4* p = (const float4*)(feats + (size_t)(e - 1) * C + c2 * 8);
    float4 f0 = __ldg(p), f1 = __ldg(p + 1);
    return make_uint4(pack2(f0.x, f0.y), pack2(f0.z, f0.w),
                      pack2(f1.x, f1.y), pack2(f1.z, f1.w));
}
__global__ void pool_z_kernel(const float* __restrict__ feats) {
    int c2   = threadIdx.x;
    int pair = blockIdx.x * blockDim.y + threadIdx.y;
    int voxbase = pair * D;
    uint4 NEG = negh4();
    uint4 w0 = NEG, w1 = NEG, w2 = NEG;
    uint4 w3 = load_point_h(feats, voxbase + 0, c2);
    uint4 w4 = load_point_h(feats, voxbase + 1, c2);
    uint4 w5 = load_point_h(feats, voxbase + 2, c2);
    uint4* out = g_bufA_h + (size_t)voxbase * 32 + c2;
    #pragma unroll 4
    for (int z = 0; z < D; z++) {
        uint4 nxt = (z + 3 < D) ? load_point_h(feats, voxbase + z + 3, c2) : NEG;
        uint4 m = hmax4(hmax4(hmax4(w0, w1), hmax4(w2, w3)),
                        hmax4(hmax4(w4, w5), nxt));
        out[(size_t)z * 32] = m;
        w0 = w1; w1 = w2; w2 = w3; w3 = w4; w4 = w5; w5 = nxt;
    }
}

// ===========================================================================
// fused y+x pass (two-phase)
// ===========================================================================
#define POOL_SMEM (64*65*16 + 4096)

__global__ void __launch_bounds__(256, 2)
pool_yx_kernel() {
    extern __shared__ uint4 ym[];
    int* idx_s = (int*)(ym + 64 * 65);

    int bid = blockIdx.x;
    int z   = bid & 63;
    int cg  = (bid >> 6) & 7;
    int y0  = (bid >> 9) * 16;
    int tid = threadIdx.x;
    uint4 NEG = negh4();

    {
        int x = tid >> 2, cq = tid & 3;
        const uint4* src = g_bufA_h + ((size_t)(x * 64) * 64 + z) * 32 + cg * 4 + cq;
        uint4 w0, w1, w2, w3, w4, w5;
        w0 = (y0 - 3 >= 0) ? src[(size_t)(y0 - 3) * 2048] : NEG;
        w1 = (y0 - 2 >= 0) ? src[(size_t)(y0 - 2) * 2048] : NEG;
        w2 = (y0 - 1 >= 0) ? src[(size_t)(y0 - 1) * 2048] : NEG;
        w3 = src[(size_t)(y0 + 0) * 2048];
        w4 = src[(size_t)(y0 + 1) * 2048];
        w5 = src[(size_t)(y0 + 2) * 2048];
        #pragma unroll 8
        for (int y = 0; y < 16; y++) {
            int yg = y0 + y + 3;
            uint4 nxt = (yg < 64) ? src[(size_t)yg * 2048] : NEG;
            uint4 m = hmax4(hmax4(hmax4(w0, w1), hmax4(w2, w3)),
                            hmax4(hmax4(w4, w5), nxt));
            ym[x * 65 + y * 4 + cq] = m;
            w0 = w1; w1 = w2; w2 = w3; w3 = w4; w4 = w5; w5 = nxt;
        }
    }
    for (int i = tid; i < 1024; i += 256) {
        int x = i >> 4, yy = i & 15;
        idx_s[i] = g_idxT[(z * 64 + x) * 64 + y0 + yy];
    }
    __syncthreads();

    {
        int cq = tid & 3, y = (tid >> 2) & 15, xq = tid >> 6;
        int x0 = xq * 16;
        int off = y * 4 + cq;
        uint4 w0, w1, w2, w3, w4, w5;
        w0 = (x0 - 3 >= 0) ? ym[(x0 - 3) * 65 + off] : NEG;
        w1 = (x0 - 2 >= 0) ? ym[(x0 - 2) * 65 + off] : NEG;
        w2 = (x0 - 1 >= 0) ? ym[(x0 - 1) * 65 + off] : NEG;
        w3 = ym[(x0 + 0) * 65 + off];
        w4 = ym[(x0 + 1) * 65 + off];
        w5 = ym[(x0 + 2) * 65 + off];
        #pragma unroll 4
        for (int xx = x0; xx < x0 + 16; xx++) {
            uint4 nxt = (xx + 3 < 64) ? ym[(xx + 3) * 65 + off] : NEG;
            int e = idx_s[xx * 16 + y];
            if (e > 0) {
                uint4 m = hmax4(hmax4(hmax4(w0, w1), hmax4(w2, w3)),
                                hmax4(hmax4(w4, w5), nxt));
                g_y4[(size_t)(e - 1) * 32 + cg * 4 + cq] = m;
            }
            w0 = w1; w1 = w2; w2 = w3; w3 = w4; w4 = w5; w5 = nxt;
        }
    }
}

// ===========================================================================
// Hybrid MLP: per-CTA path switch (tensor fp16 mma / packed f32x2 FFMA)
// ===========================================================================
__device__ __forceinline__ void mma16(float* c, unsigned a0, unsigned a1,
                                      unsigned a2, unsigned a3,
                                      unsigned b0, unsigned b1) {
    asm("mma.sync.aligned.m16n8k16.row.col.f32.f16.f16.f32 "
        "{%0,%1,%2,%3}, {%4,%5,%6,%7}, {%8,%9}, {%0,%1,%2,%3};"
        : "+f"(c[0]), "+f"(c[1]), "+f"(c[2]), "+f"(c[3])
        : "r"(a0), "r"(a1), "r"(a2), "r"(a3), "r"(b0), "r"(b1));
}
__device__ __forceinline__ void ffma2(ull& d, ull a, ull b) {
    asm("fma.rn.f32x2 %0, %1, %2, %0;" : "+l"(d) : "l"(a), "l"(b));
}
__device__ __forceinline__ ull pk64(float x, float y) {
    ull r; asm("mov.b64 %0, {%1,%2};" : "=l"(r) : "f"(x), "f"(y)); return r;
}
__device__ __forceinline__ void upk64(float& x, float& y, ull v) {
    asm("mov.b64 {%0,%1}, %2;" : "=f"(x), "=f"(y) : "l"(v));
}

// ----- tensor path (unchanged; smem <= 48KB) -----
#define OFF_XS0 0
#define OFF_XS1 8192
#define OFF_WS0 16384
#define OFF_WS1 24576
#define OFF_HS  0
#define OFF_C0  32768
#define OFF_C1  40960

__device__ __forceinline__ void t_compute(const uint4* __restrict__ A4,
                                          const uint2* __restrict__ B2,
                                          int wm, int wn, int lane,
                                          float acc[2][8][4]) {
    #pragma unroll
    for (int ks = 0; ks < 2; ks++) {
        uint4 a0 = A4[((wm * 2 + 0) * 2 + ks) * 32 + lane];
        uint4 a1 = A4[((wm * 2 + 1) * 2 + ks) * 32 + lane];
        #pragma unroll
        for (int nt = 0; nt < 8; nt++) {
            uint2 b = B2[((wn * 8 + nt) * 2 + ks) * 32 + lane];
            mma16(acc[0][nt], a0.x, a0.y, a0.z, a0.w, b.x, b.y);
            mma16(acc[1][nt], a1.x, a1.y, a1.z, a1.w, b.x, b.y);
        }
    }
}
__device__ __forceinline__ void t_ldg_X(uint4 v[2], int tid, int row0, int kt) {
    #pragma unroll
    for (int u = 0; u < 2; u++) {
        int id = tid + u * 256;
        int r = id >> 2, c8 = id & 3;
        v[u] = (row0 + r < NPTS)
             ? g_y4[(size_t)(row0 + r) * 32 + kt * 4 + c8]
             : make_uint4(0, 0, 0, 0);
    }
}
__device__ __forceinline__ void t_sts_X(unsigned* X32, int tid, const uint4 v[2]) {
    #pragma unroll
    for (int u = 0; u < 2; u++) {
        int id = tid + u * 256;
        int r = id >> 2, c8 = id & 3;
        int mb = r >> 4, g = r & 7, rb = (r >> 3) & 1;
        int ksc = c8 >> 1, kbit = c8 & 1;
        int sbase = (mb * 2 + ksc) * 32 + g * 4;
        int comp = rb + 2 * kbit;
        unsigned vv[4] = {v[u].x, v[u].y, v[u].z, v[u].w};
        #pragma unroll
        for (int j = 0; j < 4; j++)
            X32[(sbase + j) * 4 + comp] = vv[j];
    }
}
__device__ __forceinline__ void t_ldg_W(float4 v[4], int tid,
                                        const float* __restrict__ W, int ldw,
                                        int kt, int ncol0) {
    #pragma unroll
    for (int u = 0; u < 4; u++) {
        int e = tid + u * 256;
        int k = e >> 5, n4 = e & 31;
        v[u] = *(const float4*)(W + (size_t)(kt * 32 + k) * ldw + ncol0 + n4 * 4);
    }
}
__device__ __forceinline__ void t_sts_W(unsigned short* W16, int tid,
                                        const float4 v[4]) {
    #pragma unroll
    for (int u = 0; u < 4; u++) {
        int e = tid + u * 256;
        int k = e >> 5, n4 = e & 31;
        int ksc = (k >> 4) & 1, kbit = (k & 15) >> 3;
        int tg = (k & 7) >> 1, elem = k & 1;
        float vv[4] = {v[u].x, v[u].y, v[u].z, v[u].w};
        #pragma unroll
        for (int i = 0; i < 4; i++) {
            int n = n4 * 4 + i;
            int slot = ((n >> 3) * 2 + ksc) * 32 + (n & 7) * 4 + tg;
            W16[slot * 4 + kbit * 2 + elem] =
                __half_as_ushort(__float2half_rn(vv[i]));
        }
    }
}

__device__ void tensor_path(char* smb, int tid, int row0,
                            const float* __restrict__ feats,
                            const float* __restrict__ W1,
                            const float* __restrict__ W2,
                            float* __restrict__ out) {
    unsigned*       X32b[2] = {(unsigned*)(smb + OFF_XS0), (unsigned*)(smb + OFF_XS1)};
    unsigned short* W16b[2] = {(unsigned short*)(smb + OFF_WS0),
                               (unsigned short*)(smb + OFF_WS1)};
    unsigned short* C16b[2] = {(unsigned short*)(smb + OFF_C0),
                               (unsigned short*)(smb + OFF_C1)};
    unsigned* HS32 = (unsigned*)(smb + OFF_HS);

    int lane = tid & 31, wid = tid >> 5;
    int wm = wid >> 1, wn = wid & 1;
    int g = lane >> 2, tg = lane & 3;

    uint4  vx[2];
    float4 vw[4];
    float acc[2][8][4];

    #pragma unroll
    for (int mt = 0; mt < 2; mt++)
        #pragma unroll
        for (int nt = 0; nt < 8; nt++)
            #pragma unroll
            for (int q = 0; q < 4; q++) acc[mt][nt][q] = 0.f;

    t_ldg_X(vx, tid, row0, 0);
    t_ldg_W(vw, tid, W1, RDIM, 0, 0);
    t_sts_X(X32b[0], tid, vx);
    t_sts_W(W16b[0], tid, vw);
    __syncthreads();

    for (int kt = 0; kt < 8; kt++) {
        if (kt < 7) {
            t_ldg_X(vx, tid, row0, kt + 1);
            t_ldg_W(vw, tid, W1, RDIM, kt + 1, 0);
        }
        t_compute((const uint4*)X32b[kt & 1], (const uint2*)W16b[kt & 1],
                  wm, wn, lane, acc);
        if (kt < 7) {
            t_sts_X(X32b[(kt + 1) & 1], tid, vx);
            t_sts_W(W16b[(kt + 1) & 1], tid, vw);
        }
        __syncthreads();
    }

    #pragma unroll
    for (int mt = 0; mt < 2; mt++) {
        #pragma unroll
        for (int nt = 0; nt < 8; nt++) {
            int mb = wm * 2 + mt;
            int kc = wn * 2 + (nt >> 2);
            unsigned* Hc = HS32 + kc * 2048;
            int slot = (mb * 2 + ((nt & 3) >> 1)) * 32 + g * 4 + tg;
            Hc[slot * 4 + 2 * (nt & 1)] =
                pack2(fmaxf(acc[mt][nt][0], 0.f), fmaxf(acc[mt][nt][1], 0.f));
            Hc[slot * 4 + 1 + 2 * (nt & 1)] =
                pack2(fmaxf(acc[mt][nt][2], 0.f), fmaxf(acc[mt][nt][3], 0.f));
        }
    }
    __syncthreads();

    for (int half = 0; half < 2; half++) {
        #pragma unroll
        for (int mt = 0; mt < 2; mt++)
            #pragma unroll
            for (int nt = 0; nt < 8; nt++)
                #pragma unroll
                for (int q = 0; q < 4; q++) acc[mt][nt][q] = 0.f;

        t_ldg_W(vw, tid, W2, C, 0, half * 128);
        t_sts_W(C16b[0], tid, vw);
        __syncthreads();

        for (int kc = 0; kc < 4; kc++) {
            if (kc < 3) t_ldg_W(vw, tid, W2, C, kc + 1, half * 128);
            t_compute((const uint4*)(HS32 + kc * 2048),
                      (const uint2*)C16b[kc & 1], wm, wn, lane, acc);
            if (kc < 3) t_sts_W(C16b[(kc + 1) & 1], tid, vw);
            __syncthreads();
        }

        #pragma unroll
        for (int mt = 0; mt < 2; mt++) {
            #pragma unroll
            for (int nt = 0; nt < 8; nt++) {
                int rr = wm * 32 + mt * 16 + g;
                int cc = half * 128 + wn * 64 + nt * 8 + 2 * tg;
                #pragma unroll
                for (int h = 0; h < 2; h++) {
                    int row = row0 + rr + h * 8;
                    if (row < NPTS) {
                        float z0 = acc[mt][nt][h * 2 + 0];
                        float z1 = acc[mt][nt][h * 2 + 1];
                        float2 fv = *(const float2*)(feats + (size_t)row * C + cc);
                        float2 o;
                        o.x = fv.x / (1.f + __expf(-z0));
                        o.y = fv.y / (1.f + __expf(-z1));
                        *(float2*)(out + (size_t)row * C + cc) = o;
                    }
                }
            }
        }
    }
}

// ----- f32x2 path: conflict-free layout -----
// Thread (tx,ty): rows ty*8..+7, cols {tx*4..+3} and {64+tx*4..+3}.
// X/W tiles: [k:32][128] stride 128 (16KB). B-read = 2 conflict-free LDS.128.
// H stored row-major [row:128][h:128] (write conflict-free, read broadcast).
#define FX0 0
#define FX1 16384
#define FW0 32768
#define FW1 49152
#define FHS 0
#define FC0 65536
#define FC1 81920
#define HYB_SMEM 98304

__device__ __forceinline__ void f_ldg_X(uint4 v[2], int tid, int row0, int kt) {
    int r = tid & 127, half = tid >> 7;
    int row = row0 + r;
    if (row < NPTS) {
        const uint4* p = g_y4 + (size_t)row * 32 + kt * 4 + half * 2;
        v[0] = p[0]; v[1] = p[1];
    } else {
        v[0] = v[1] = make_uint4(0, 0, 0, 0);
    }
}
__device__ __forceinline__ void f_sts_X(float* Xs, int tid, const uint4 v[2]) {
    int r = tid & 127, half = tid >> 7;
    float* dst = Xs + half * 16 * 128 + r;
    unsigned w[8] = {v[0].x, v[0].y, v[0].z, v[0].w,
                     v[1].x, v[1].y, v[1].z, v[1].w};
    #pragma unroll
    for (int q = 0; q < 8; q++) {
        float2 f = __half22float2(*reinterpret_cast<const __half2*>(&w[q]));
        dst[(q * 2 + 0) * 128] = f.x;
        dst[(q * 2 + 1) * 128] = f.y;
    }
}
__device__ __forceinline__ void f_ldg_W(float4 v[4], int tid,
                                        const float* __restrict__ W, int ldw,
                                        int kt, int ncol0) {
    #pragma unroll
    for (int u = 0; u < 4; u++) {
        int e = tid + u * 256;
        int k = e >> 5, n4 = e & 31;
        v[u] = *(const float4*)(W + (size_t)(kt * 32 + k) * ldw + ncol0 + n4 * 4);
    }
}
__device__ __forceinline__ void f_sts_W(float* Ws, int tid, const float4 v[4]) {
    #pragma unroll
    for (int u = 0; u < 4; u++) {
        int e = tid + u * 256;
        int k = e >> 5, n4 = e & 31;
        *(float4*)(Ws + k * 128 + n4 * 4) = v[u];
    }
}
// GEMM1 chunk: Xs [k][row], Ws [k][n]
__device__ __forceinline__ void f_compute(const float* __restrict__ Xs,
                                          const float* __restrict__ Ws,
                                          int tx, int ty, ull acc[8][4]) {
    #pragma unroll 4
    for (int k = 0; k < 32; k++) {
        float4 a0 = *(const float4*)(Xs + k * 128 + ty * 8);
        float4 a1 = *(const float4*)(Xs + k * 128 + ty * 8 + 4);
        float4 b0 = *(const float4*)(Ws + k * 128 + tx * 4);
        float4 b1 = *(const float4*)(Ws + k * 128 + 64 + tx * 4);
        ull bv[4] = {pk64(b0.x, b0.y), pk64(b0.z, b0.w),
                     pk64(b1.x, b1.y), pk64(b1.z, b1.w)};
        float av[8] = {a0.x, a0.y, a0.z, a0.w, a1.x, a1.y, a1.z, a1.w};
        #pragma unroll
        for (int i = 0; i < 8; i++) {
            ull ad = pk64(av[i], av[i]);
            #pragma unroll
            for (int j = 0; j < 4; j++) ffma2(acc[i][j], ad, bv[j]);
        }
    }
}
// GEMM2 chunk: HS row-major [row][h], k window k0..k0+31; Ws [k][n]
__device__ __forceinline__ void f_compute2(const float* __restrict__ HS,
                                           int k0,
                                           const float* __restrict__ Ws,
                                           int tx, int ty, ull acc[8][4]) {
    #pragma unroll 2
    for (int kp = 0; kp < 16; kp++) {
        int k = kp * 2;
        float2 a2[8];
        #pragma unroll
        for (int i = 0; i < 8; i++)
            a2[i] = *(const float2*)(HS + (ty * 8 + i) * 128 + k0 + k);
        #pragma unroll
        for (int kk = 0; kk < 2; kk++) {
            float4 b0 = *(const float4*)(Ws + (k + kk) * 128 + tx * 4);
            float4 b1 = *(const float4*)(Ws + (k + kk) * 128 + 64 + tx * 4);
            ull bv[4] = {pk64(b0.x, b0.y), pk64(b0.z, b0.w),
                         pk64(b1.x, b1.y), pk64(b1.z, b1.w)};
            #pragma unroll
            for (int i = 0; i < 8; i++) {
                float a = kk ? a2[i].y : a2[i].x;
                ull ad = pk64(a, a);
                #pragma unroll
                for (int j = 0; j < 4; j++) ffma2(acc[i][j], ad, bv[j]);
            }
        }
    }
}

__device__ void fma_path(char* smb, int tid, int row0,
                         const float* __restrict__ feats,
                         const float* __restrict__ W1,
                         const float* __restrict__ W2,
                         float* __restrict__ out) {
    float* Xb[2] = {(float*)(smb + FX0), (float*)(smb + FX1)};
    float* Wb[2] = {(float*)(smb + FW0), (float*)(smb + FW1)};
    float* Cb[2] = {(float*)(smb + FC0), (float*)(smb + FC1)};
    float* HS    = (float*)(smb + FHS);

    int tx = tid & 15, ty = tid >> 4;

    uint4  vx[2];
    float4 vw[4];
    ull acc[8][4];

    // ---------------- GEMM1: H = relu(Y @ W1), K=256, 8 chunks --------------
    #pragma unroll
    for (int i = 0; i < 8; i++)
        #pragma unroll
        for (int j = 0; j < 4; j++) acc[i][j] = 0ull;

    f_ldg_X(vx, tid, row0, 0);
    f_ldg_W(vw, tid, W1, RDIM, 0, 0);
    f_sts_X(Xb[0], tid, vx);
    f_sts_W(Wb[0], tid, vw);
    __syncthreads();

    for (int kt = 0; kt < 8; kt++) {
        if (kt < 7) {
            f_ldg_X(vx, tid, row0, kt + 1);
            f_ldg_W(vw, tid, W1, RDIM, kt + 1, 0);
        }
        f_compute(Xb[kt & 1], Wb[kt & 1], tx, ty, acc);
        if (kt < 7) {
            f_sts_X(Xb[(kt + 1) & 1], tid, vx);
            f_sts_W(Wb[(kt + 1) & 1], tid, vw);
        }
        __syncthreads();
    }

    // relu -> HS[row][h] (conflict-free STS.128; aliases X/W bufs)
    #pragma unroll
    for (int i = 0; i < 8; i++) {
        int row = ty * 8 + i;
        float x0, y0c, x1, y1;
        upk64(x0, y0c, acc[i][0]);
        upk64(x1, y1, acc[i][1]);
        float4 h0 = make_float4(fmaxf(x0, 0.f), fmaxf(y0c, 0.f),
                                fmaxf(x1, 0.f), fmaxf(y1, 0.f));
        upk64(x0, y0c, acc[i][2]);
        upk64(x1, y1, acc[i][3]);
        float4 h1 = make_float4(fmaxf(x0, 0.f), fmaxf(y0c, 0.f),
                                fmaxf(x1, 0.f), fmaxf(y1, 0.f));
        *(float4*)(HS + row * 128 + tx * 4)      = h0;
        *(float4*)(HS + row * 128 + 64 + tx * 4) = h1;
    }
    __syncthreads();

    // ------------- GEMM2: O = H @ W2 (K=128), two 128-col halves ------------
    for (int half = 0; half < 2; half++) {
        #pragma unroll
        for (int i = 0; i < 8; i++)
            #pragma unroll
            for (int j = 0; j < 4; j++) acc[i][j] = 0ull;

        f_ldg_W(vw, tid, W2, C, 0, half * 128);
        f_sts_W(Cb[0], tid, vw);
        __syncthreads();

        for (int kc = 0; kc < 4; kc++) {
            if (kc < 3) f_ldg_W(vw, tid, W2, C, kc + 1, half * 128);
            f_compute2(HS, kc * 32, Cb[kc & 1], tx, ty, acc);
            if (kc < 3) f_sts_W(Cb[(kc + 1) & 1], tid, vw);
            __syncthreads();
        }

        // epilogue: out = feats * sigmoid(acc); float4 coalesced stores
        #pragma unroll
        for (int i = 0; i < 8; i++) {
            int row = row0 + ty * 8 + i;
            if (row < NPTS) {
                #pragma unroll
                for (int ch = 0; ch < 2; ch++) {
                    int cc = half * 128 + ch * 64 + tx * 4;
                    float z0, z1, z2, z3;
                    upk64(z0, z1, acc[i][ch * 2 + 0]);
                    upk64(z2, z3, acc[i][ch * 2 + 1]);
                    float4 fv = *(const float4*)(feats + (size_t)row * C + cc);
                    float4 o;
                    o.x = fv.x / (1.f + __expf(-z0));
                    o.y = fv.y / (1.f + __expf(-z1));
                    o.z = fv.z / (1.f + __expf(-z2));
                    o.w = fv.w / (1.f + __expf(-z3));
                    *(float4*)(out + (size_t)row * C + cc) = o;
                }
            }
        }
    }
}

__global__ void __launch_bounds__(256, 2)
mlp_hybrid_kernel(const float* __restrict__ feats,
                  const float* __restrict__ W1,
                  const float* __restrict__ W2,
                  float* __restrict__ out) {
    extern __shared__ char smb[];
    int tid = threadIdx.x;
    int bid = blockIdx.x;
    int row0 = bid * 128;
    int m = bid & 7;
    bool use_tensor = (m == 1) || (m == 4) || (m == 6);   // 3/8 tensor
    if (use_tensor)
        tensor_path(smb, tid, row0, feats, W1, W2, out);
    else
        fma_path(smb, tid, row0, feats, W1, W2, out);
}

// ===========================================================================
extern "C" void kernel_launch(void* const* d_in, const int* in_sizes, int n_in,
                              void* d_out, int out_size) {
    const float* feats  = (const float*)d_in[0];
    const int*   coords = (const int*)d_in[1];
    const float* W1     = (const float*)d_in[2];
    const float* W2     = (const float*)d_in[3];
    float*       out    = (float*)d_out;

    scatter_idx_kernel<<<(NPTS + 255)/256, 256>>>(coords);

    dim3 zt(32, 8);
    pool_z_kernel<<<D*D/8, zt>>>(feats);

    cudaFuncSetAttribute(pool_yx_kernel,
                         cudaFuncAttributeMaxDynamicSharedMemorySize, POOL_SMEM);
    pool_yx_kernel<<<64 * 8 * 4, 256, POOL_SMEM>>>();

    cudaFuncSetAttribute(mlp_hybrid_kernel,
                         cudaFuncAttributeMaxDynamicSharedMemorySize, HYB_SMEM);
    mlp_hybrid_kernel<<<(NPTS + 127)/128, 256, HYB_SMEM>>>(feats, W1, W2, out);
}

// round 14
// speedup vs baseline: 2.1599x; 2.0912x over previous
#include <cuda_runtime.h>
#include <cuda_bf16.h>
#include <cuda_fp16.h>

#define D     64
#define C     256
#define RDIM  128
#define NPTS  100000
#define GRID_VOX (D*D*D)

typedef unsigned long long ull;

// ---- scratch (device globals; BSS zero-initialized; no allocation) ----
__device__ int   g_idx[GRID_VOX];                 // (x*64+y)*64+z -> point+1, 0=empty
__device__ int   g_idxT[GRID_VOX];                // (z*64+x)*64+y -> point+1
__device__ uint4 g_bufA_h[(size_t)GRID_VOX * 32]; // z-pooled grid, fp16
__device__ uint4 g_y4[(size_t)NPTS * 32];         // pooled, compacted, fp16
__device__ uint2 g_w1f[8 * 1024];                 // W1 fp16 B-frag layout (8 chunks)
__device__ uint2 g_w2f[8 * 1024];                 // W2 fp16 B-frag layout (2 halves x 4)

#define NEGH 0xFC00FC00u
__device__ __forceinline__ uint4 negh4() { return make_uint4(NEGH, NEGH, NEGH, NEGH); }

__device__ __forceinline__ unsigned h2max(unsigned a, unsigned b) {
    __half2 r = __hmax2(*reinterpret_cast<__half2*>(&a),
                        *reinterpret_cast<__half2*>(&b));
    return *reinterpret_cast<unsigned*>(&r);
}
__device__ __forceinline__ uint4 hmax4(uint4 a, uint4 b) {
    return make_uint4(h2max(a.x, b.x), h2max(a.y, b.y),
                      h2max(a.z, b.z), h2max(a.w, b.w));
}
__device__ __forceinline__ unsigned pack2(float a, float b) {
    __half2 h = __floats2half2_rn(a, b);
    return *reinterpret_cast<unsigned*>(&h);
}

// ===========================================================================
// scatter (0 = empty, value = point index + 1; BSS gives the zero init)
// ===========================================================================
__global__ void scatter_idx_kernel(const int* __restrict__ coords) {
    int n = blockIdx.x * blockDim.x + threadIdx.x;
    if (n < NPTS) {
        int ix = coords[3*n+0], iy = coords[3*n+1], iz = coords[3*n+2];
        g_idx[(ix*D + iy)*D + iz] = n + 1;
        g_idxT[(iz*D + ix)*D + iy] = n + 1;
    }
}

// ===========================================================================
// weight prep: W1/W2 fp32 -> fp16 mma B-fragment layout in global
// block b: 0..7 = W1 chunk b; 8..15 = W2 (half = (b-8)>>2, kc = (b-8)&3)
// ===========================================================================
__global__ void w_prep_kernel(const float* __restrict__ W1,
                              const float* __restrict__ W2) {
    int b = blockIdx.x;
    const float* W; int ldw, krow0, ncol0; uint2* dst;
    if (b < 8) { W = W1; ldw = RDIM; krow0 = b * 32; ncol0 = 0; dst = g_w1f + b * 1024; }
    else {
        int idx = b - 8;
        W = W2; ldw = C; krow0 = (idx & 3) * 32; ncol0 = (idx >> 2) * 128;
        dst = g_w2f + idx * 1024;
    }
    for (int s = threadIdx.x; s < 1024; s += blockDim.x) {
        int lane = s & 31, nbk = s >> 5;
        int g = lane >> 2, tg = lane & 3;
        int n = (nbk >> 1) * 8 + g, ksc = nbk & 1;
        unsigned h[4];
        #pragma unroll
        for (int kbit = 0; kbit < 2; kbit++)
            #pragma unroll
            for (int elem = 0; elem < 2; elem++) {
                int k = ksc * 16 + kbit * 8 + tg * 2 + elem;
                h[kbit * 2 + elem] = (unsigned)__half_as_ushort(
                    __float2half_rn(W[(size_t)(krow0 + k) * ldw + ncol0 + n]));
            }
        uint2 v; v.x = h[0] | (h[1] << 16); v.y = h[2] | (h[3] << 16);
        dst[s] = v;
    }
}

// ===========================================================================
// z-pass
// ===========================================================================
__device__ __forceinline__ uint4 load_point_h(const float* __restrict__ feats,
                                              int vox, int c2) {
    int e = g_idx[vox];
    if (e == 0) return negh4();
    const float4* p = (const float4*)(feats + (size_t)(e - 1) * C + c2 * 8);
    float4 f0 = __ldg(p), f1 = __ldg(p + 1);
    return make_uint4(pack2(f0.x, f0.y), pack2(f0.z, f0.w),
                      pack2(f1.x, f1.y), pack2(f1.z, f1.w));
}
__global__ void pool_z_kernel(const float* __restrict__ feats) {
    int c2   = threadIdx.x;
    int pair = blockIdx.x * blockDim.y + threadIdx.y;
    int voxbase = pair * D;
    uint4 NEG = negh4();
    uint4 w0 = NEG, w1 = NEG, w2 = NEG;
    uint4 w3 = load_point_h(feats, voxbase + 0, c2);
    uint4 w4 = load_point_h(feats, voxbase + 1, c2);
    uint4 w5 = load_point_h(feats, voxbase + 2, c2);
    uint4* out = g_bufA_h + (size_t)voxbase * 32 + c2;
    #pragma unroll 4
    for (int z = 0; z < D; z++) {
        uint4 nxt = (z + 3 < D) ? load_point_h(feats, voxbase + z + 3, c2) : NEG;
        uint4 m = hmax4(hmax4(hmax4(w0, w1), hmax4(w2, w3)),
                        hmax4(hmax4(w4, w5), nxt));
        out[(size_t)z * 32] = m;
        w0 = w1; w1 = w2; w2 = w3; w3 = w4; w4 = w5; w5 = nxt;
    }
}

// ===========================================================================
// fused y+x pass (two-phase)
// ===========================================================================
#define POOL_SMEM (64*65*16 + 4096)

__global__ void __launch_bounds__(256, 2)
pool_yx_kernel() {
    extern __shared__ uint4 ym[];
    int* idx_s = (int*)(ym + 64 * 65);

    int bid = blockIdx.x;
    int z   = bid & 63;
    int cg  = (bid >> 6) & 7;
    int y0  = (bid >> 9) * 16;
    int tid = threadIdx.x;
    uint4 NEG = negh4();

    {
        int x = tid >> 2, cq = tid & 3;
        const uint4* src = g_bufA_h + ((size_t)(x * 64) * 64 + z) * 32 + cg * 4 + cq;
        uint4 w0, w1, w2, w3, w4, w5;
        w0 = (y0 - 3 >= 0) ? src[(size_t)(y0 - 3) * 2048] : NEG;
        w1 = (y0 - 2 >= 0) ? src[(size_t)(y0 - 2) * 2048] : NEG;
        w2 = (y0 - 1 >= 0) ? src[(size_t)(y0 - 1) * 2048] : NEG;
        w3 = src[(size_t)(y0 + 0) * 2048];
        w4 = src[(size_t)(y0 + 1) * 2048];
        w5 = src[(size_t)(y0 + 2) * 2048];
        #pragma unroll 8
        for (int y = 0; y < 16; y++) {
            int yg = y0 + y + 3;
            uint4 nxt = (yg < 64) ? src[(size_t)yg * 2048] : NEG;
            uint4 m = hmax4(hmax4(hmax4(w0, w1), hmax4(w2, w3)),
                            hmax4(hmax4(w4, w5), nxt));
            ym[x * 65 + y * 4 + cq] = m;
            w0 = w1; w1 = w2; w2 = w3; w3 = w4; w4 = w5; w5 = nxt;
        }
    }
    for (int i = tid; i < 1024; i += 256) {
        int x = i >> 4, yy = i & 15;
        idx_s[i] = g_idxT[(z * 64 + x) * 64 + y0 + yy];
    }
    __syncthreads();

    {
        int cq = tid & 3, y = (tid >> 2) & 15, xq = tid >> 6;
        int x0 = xq * 16;
        int off = y * 4 + cq;
        uint4 w0, w1, w2, w3, w4, w5;
        w0 = (x0 - 3 >= 0) ? ym[(x0 - 3) * 65 + off] : NEG;
        w1 = (x0 - 2 >= 0) ? ym[(x0 - 2) * 65 + off] : NEG;
        w2 = (x0 - 1 >= 0) ? ym[(x0 - 1) * 65 + off] : NEG;
        w3 = ym[(x0 + 0) * 65 + off];
        w4 = ym[(x0 + 1) * 65 + off];
        w5 = ym[(x0 + 2) * 65 + off];
        #pragma unroll 4
        for (int xx = x0; xx < x0 + 16; xx++) {
            uint4 nxt = (xx + 3 < 64) ? ym[(xx + 3) * 65 + off] : NEG;
            int e = idx_s[xx * 16 + y];
            if (e > 0) {
                uint4 m = hmax4(hmax4(hmax4(w0, w1), hmax4(w2, w3)),
                                hmax4(hmax4(w4, w5), nxt));
                g_y4[(size_t)(e - 1) * 32 + cg * 4 + cq] = m;
            }
            w0 = w1; w1 = w2; w2 = w3; w3 = w4; w4 = w5; w5 = nxt;
        }
    }
}

// ===========================================================================
// MLP: fp16 mma.sync, 128-thread CTAs, 64-row blocks, B-frags via LDG,
// X via smem double-buffer, HS aliased, 16KB smem -> 4 CTAs/SM
// ===========================================================================
__device__ __forceinline__ void mma16(float* c, unsigned a0, unsigned a1,
                                      unsigned a2, unsigned a3,
                                      unsigned b0, unsigned b1) {
    asm("mma.sync.aligned.m16n8k16.row.col.f32.f16.f16.f32 "
        "{%0,%1,%2,%3}, {%4,%5,%6,%7}, {%8,%9}, {%0,%1,%2,%3};"
        : "+f"(c[0]), "+f"(c[1]), "+f"(c[2]), "+f"(c[3])
        : "r"(a0), "r"(a1), "r"(a2), "r"(a3), "r"(b0), "r"(b1));
}

#define MLP2_SMEM 16384

// B-frag load: 8 uint2 per warp-thread for one 32-k chunk (warp n-slice 32)
__device__ __forceinline__ void ldg_B(uint2 dst[8], const uint2* __restrict__ tbl,
                                      int chunk, int wn, int lane) {
    const uint2* base = tbl + chunk * 1024 + wn * 256 + lane;
    #pragma unroll
    for (int e = 0; e < 8; e++) dst[e] = __ldg(base + e * 32);
}
// X tile: 64 rows x 32 k fp16 per chunk
__device__ __forceinline__ void ldg_X2(uint4 v[2], int tid, int row0, int kt) {
    #pragma unroll
    for (int u = 0; u < 2; u++) {
        int id = tid + u * 128;
        int r = id >> 2, c8 = id & 3;
        v[u] = (row0 + r < NPTS)
             ? g_y4[(size_t)(row0 + r) * 32 + kt * 4 + c8]
             : make_uint4(0, 0, 0, 0);
    }
}
__device__ __forceinline__ void sts_X2(unsigned* X32, int tid, const uint4 v[2]) {
    #pragma unroll
    for (int u = 0; u < 2; u++) {
        int id = tid + u * 128;
        int r = id >> 2, c8 = id & 3;
        int mb = r >> 4, g = r & 7, rb = (r >> 3) & 1;
        int ksc = c8 >> 1, kbit = c8 & 1;
        int sbase = (mb * 2 + ksc) * 32 + g * 4;
        int comp = rb + 2 * kbit;
        unsigned vv[4] = {v[u].x, v[u].y, v[u].z, v[u].w};
        #pragma unroll
        for (int j = 0; j < 4; j++)
            X32[(sbase + j) * 4 + comp] = vv[j];
    }
}
// one 32-k chunk: A-frags from smem (64 rows), B-frags from regs (n-slice 32)
__device__ __forceinline__ void computeA(const uint4* __restrict__ A4,
                                         const uint2 b8[8], int lane,
                                         float acc[4][4][4]) {
    #pragma unroll
    for (int ks = 0; ks < 2; ks++) {
        uint4 Af[4];
        #pragma unroll
        for (int mb = 0; mb < 4; mb++) Af[mb] = A4[(mb * 2 + ks) * 32 + lane];
        #pragma unroll
        for (int nbl = 0; nbl < 4; nbl++) {
            uint2 b = b8[nbl * 2 + ks];
            #pragma unroll
            for (int mb = 0; mb < 4; mb++)
                mma16(acc[mb][nbl], Af[mb].x, Af[mb].y, Af[mb].z, Af[mb].w,
                      b.x, b.y);
        }
    }
}

__global__ void __launch_bounds__(128, 4)
mlp_tc2_kernel(const float* __restrict__ feats, float* __restrict__ out) {
    extern __shared__ char smb[];
    unsigned* Xb[2] = {(unsigned*)smb, (unsigned*)(smb + 4096)};
    unsigned* HS32  = (unsigned*)smb;              // 16KB, aliases Xb

    int tid = threadIdx.x, lane = tid & 31, wn = tid >> 5;
    int g = lane >> 2, tg = lane & 3;
    int row0 = blockIdx.x * 64;

    float acc[4][4][4];
    uint4 vx[2];
    uint2 br[2][8];

    // ---------------- GEMM1: H = relu(Y @ W1), K=256, 8 chunks --------------
    #pragma unroll
    for (int mb = 0; mb < 4; mb++)
        #pragma unroll
        for (int nbl = 0; nbl < 4; nbl++)
            #pragma unroll
            for (int q = 0; q < 4; q++) acc[mb][nbl][q] = 0.f;

    ldg_X2(vx, tid, row0, 0);
    ldg_B(br[0], g_w1f, 0, wn, lane);
    sts_X2(Xb[0], tid, vx);
    __syncthreads();

    #pragma unroll
    for (int kt = 0; kt < 8; kt++) {
        if (kt < 7) {
            ldg_X2(vx, tid, row0, kt + 1);
            ldg_B(br[(kt + 1) & 1], g_w1f, kt + 1, wn, lane);
        }
        computeA((const uint4*)Xb[kt & 1], br[kt & 1], lane, acc);
        if (kt < 7) sts_X2(Xb[(kt + 1) & 1], tid, vx);
        __syncthreads();
    }

    // epilogue 1: relu -> HS fp16 A-frag layout; warp wn owns k-chunk wn
    {
        unsigned* Hc = HS32 + wn * 1024;
        #pragma unroll
        for (int mb = 0; mb < 4; mb++)
            #pragma unroll
            for (int nbl = 0; nbl < 4; nbl++) {
                int slot = (mb * 2 + (nbl >> 1)) * 32 + lane;
                uint2 v;
                v.x = pack2(fmaxf(acc[mb][nbl][0], 0.f),
                            fmaxf(acc[mb][nbl][1], 0.f));
                v.y = pack2(fmaxf(acc[mb][nbl][2], 0.f),
                            fmaxf(acc[mb][nbl][3], 0.f));
                // comps (rb=0, rb=1) at kbit = nbl&1
                Hc[slot * 4 + 2 * (nbl & 1) + 0] = v.x;
                Hc[slot * 4 + 2 * (nbl & 1) + 1] = v.y;
            }
    }
    __syncthreads();

    // ------------- GEMM2: O = H @ W2 (K=128), two 128-col halves ------------
    ldg_B(br[0], g_w2f, 0, wn, lane);

    #pragma unroll
    for (int half = 0; half < 2; half++) {
        #pragma unroll
        for (int mb = 0; mb < 4; mb++)
            #pragma unroll
            for (int nbl = 0; nbl < 4; nbl++)
                #pragma unroll
                for (int q = 0; q < 4; q++) acc[mb][nbl][q] = 0.f;

        #pragma unroll
        for (int kc = 0; kc < 4; kc++) {
            int idx = half * 4 + kc;
            if (idx < 7) ldg_B(br[(idx + 1) & 1], g_w2f, idx + 1, wn, lane);
            computeA((const uint4*)HS32 + kc * 256, br[idx & 1], lane, acc);
        }

        // epilogue 2: out = feats * sigmoid(acc)
        #pragma unroll
        for (int mb = 0; mb < 4; mb++) {
            #pragma unroll
            for (int nbl = 0; nbl < 4; nbl++) {
                int cc = half * 128 + wn * 32 + nbl * 8 + 2 * tg;
                #pragma unroll
                for (int rb = 0; rb < 2; rb++) {
                    int row = row0 + mb * 16 + rb * 8 + g;
                    if (row < NPTS) {
                        float z0 = acc[mb][nbl][rb * 2 + 0];
                        float z1 = acc[mb][nbl][rb * 2 + 1];
                        float2 fv = *(const float2*)(feats + (size_t)row * C + cc);
                        float2 o;
                        o.x = fv.x / (1.f + __expf(-z0));
                        o.y = fv.y / (1.f + __expf(-z1));
                        *(float2*)(out + (size_t)row * C + cc) = o;
                    }
                }
            }
        }
    }
}

// ===========================================================================
extern "C" void kernel_launch(void* const* d_in, const int* in_sizes, int n_in,
                              void* d_out, int out_size) {
    const float* feats  = (const float*)d_in[0];
    const int*   coords = (const int*)d_in[1];
    const float* W1     = (const float*)d_in[2];
    const float* W2     = (const float*)d_in[3];
    float*       out    = (float*)d_out;

    scatter_idx_kernel<<<(NPTS + 255)/256, 256>>>(coords);
    w_prep_kernel<<<16, 256>>>(W1, W2);

    dim3 zt(32, 8);
    pool_z_kernel<<<D*D/8, zt>>>(feats);

    cudaFuncSetAttribute(pool_yx_kernel,
                         cudaFuncAttributeMaxDynamicSharedMemorySize, POOL_SMEM);
    pool_yx_kernel<<<64 * 8 * 4, 256, POOL_SMEM>>>();

    cudaFuncSetAttribute(mlp_tc2_kernel,
                         cudaFuncAttributeMaxDynamicSharedMemorySize, MLP2_SMEM);
    mlp_tc2_kernel<<<(NPTS + 63)/64, 128, MLP2_SMEM>>>(feats, out);
}